// round 2
// baseline (speedup 1.0000x reference)
#include <cuda_runtime.h>
#include <math.h>

// Problem constants
#define Bsz 2
#define Sq  2048
#define Dm  1024
#define Hn  16
#define HDm 64
// 3*Dm = 3072 per-token qkv row

// Scratch (allocation-free rule: __device__ globals)
__device__ float g_qkv[(size_t)Bsz * Sq * 3 * Dm];   // [B, S, 3D]  (50.3 MB)
__device__ float g_att[(size_t)Bsz * Sq * Dm];       // [B][H][S][HD] contiguous (16.8 MB)

// ----------------------------------------------------------------------------
// Tiled fp32 GEMM with bias: C[M,N] = A[M,K] @ B[K,N] + bias[N]
// BM=BN=128, BK=16, 256 threads, 8x8 register tile per thread.
// All dims here are multiples of the tile sizes (4096/3072/1024), no guards.
// ----------------------------------------------------------------------------
__global__ __launch_bounds__(256) void sgemm_bias(
    int M, int N, int K,
    const float* __restrict__ A, const float* __restrict__ B,
    const float* __restrict__ bias, float* __restrict__ C)
{
    __shared__ float As[16][132];   // [k][row], padded
    __shared__ float Bs[16][128];   // [k][col]

    const int tid  = threadIdx.x;
    const int tcol = tid & 15;      // 0..15
    const int trow = tid >> 4;      // 0..15
    const int bx = blockIdx.x * 128;
    const int by = blockIdx.y * 128;

    float acc[8][8];
#pragma unroll
    for (int i = 0; i < 8; i++)
#pragma unroll
        for (int j = 0; j < 8; j++) acc[i][j] = 0.f;

    for (int k0 = 0; k0 < K; k0 += 16) {
        // A tile: 128x16, transposed store
#pragma unroll
        for (int t = tid; t < 512; t += 256) {
            int r  = t >> 2;
            int c4 = t & 3;
            float4 v = *(const float4*)(A + (size_t)(by + r) * K + k0 + c4 * 4);
            As[c4 * 4 + 0][r] = v.x;
            As[c4 * 4 + 1][r] = v.y;
            As[c4 * 4 + 2][r] = v.z;
            As[c4 * 4 + 3][r] = v.w;
        }
        // B tile: 16x128
#pragma unroll
        for (int t = tid; t < 512; t += 256) {
            int r  = t >> 5;
            int c4 = t & 31;
            *(float4*)(&Bs[r][c4 * 4]) =
                *(const float4*)(B + (size_t)(k0 + r) * N + bx + c4 * 4);
        }
        __syncthreads();

#pragma unroll
        for (int k = 0; k < 16; k++) {
            float4 a0 = *(const float4*)(&As[k][trow * 8]);
            float4 a1 = *(const float4*)(&As[k][trow * 8 + 4]);
            float4 b0 = *(const float4*)(&Bs[k][tcol * 8]);
            float4 b1 = *(const float4*)(&Bs[k][tcol * 8 + 4]);
            float ar[8] = {a0.x, a0.y, a0.z, a0.w, a1.x, a1.y, a1.z, a1.w};
            float br[8] = {b0.x, b0.y, b0.z, b0.w, b1.x, b1.y, b1.z, b1.w};
#pragma unroll
            for (int i = 0; i < 8; i++)
#pragma unroll
                for (int j = 0; j < 8; j++)
                    acc[i][j] = fmaf(ar[i], br[j], acc[i][j]);
        }
        __syncthreads();
    }

#pragma unroll
    for (int i = 0; i < 8; i++) {
        int row = by + trow * 8 + i;
#pragma unroll
        for (int j4 = 0; j4 < 2; j4++) {
            int col = bx + tcol * 8 + j4 * 4;
            float4 bv = *(const float4*)(bias + col);
            float4 o;
            o.x = acc[i][j4 * 4 + 0] + bv.x;
            o.y = acc[i][j4 * 4 + 1] + bv.y;
            o.z = acc[i][j4 * 4 + 2] + bv.z;
            o.w = acc[i][j4 * 4 + 3] + bv.w;
            *(float4*)(C + (size_t)row * N + col) = o;
        }
    }
}

// ----------------------------------------------------------------------------
// Flash attention (fp32, causal). One CTA = one (b,h, 64-row Q block).
// Online softmax; iterates only over kv blocks jb <= qb (causal skip).
// Output written contiguously as [B][H][S][HD] -- this IS the reference's
// raw reshape (values.reshape(b, s, H*HD) with no transpose back).
// smem tiles [64][68] fp32: Qs (transposed, pre-scaled), KP (K then reused
// for P), Vs. 3*64*68*4 = 52224 B dynamic smem.
// ----------------------------------------------------------------------------
__global__ __launch_bounds__(256) void flash_attn(
    const float* __restrict__ qkv, float* __restrict__ att)
{
    extern __shared__ float sm[];
    float* Qs = sm;                  // [hd][row], stride 68, pre-scaled by 1/8
    float* KP = sm + 64 * 68;        // K: [hd][col] ; P: [row][kv]
    float* Vs = sm + 2 * 64 * 68;    // [kv][hd]

    const int bh = blockIdx.y;       // b*16 + h
    const int b  = bh >> 4;
    const int h  = bh & 15;
    const int qb = blockIdx.x;       // 0..31
    const int tid = threadIdx.x;
    const int tx = tid & 15;
    const int ty = tid >> 4;

    const size_t base = (size_t)b * Sq * 3072 + (size_t)h * 192;

    // Load Q tile (64 rows x 64 hd), transposed + pre-scaled
#pragma unroll
    for (int t = tid; t < 1024; t += 256) {
        int r = t >> 4, k4 = t & 15;
        float4 v = *(const float4*)(qkv + base + (size_t)(qb * 64 + r) * 3072 + k4 * 4);
        Qs[(k4 * 4 + 0) * 68 + r] = v.x * 0.125f;
        Qs[(k4 * 4 + 1) * 68 + r] = v.y * 0.125f;
        Qs[(k4 * 4 + 2) * 68 + r] = v.z * 0.125f;
        Qs[(k4 * 4 + 3) * 68 + r] = v.w * 0.125f;
    }

    float m[4], l[4], o[4][4];
#pragma unroll
    for (int i = 0; i < 4; i++) {
        m[i] = -3.0e38f; l[i] = 0.f;
#pragma unroll
        for (int j = 0; j < 4; j++) o[i][j] = 0.f;
    }

    for (int jb = 0; jb <= qb; jb++) {
        __syncthreads();   // prior P/V reads done (and Q load on iter 0)

        // Load K (transposed) and V tiles for kv block jb
#pragma unroll
        for (int t = tid; t < 1024; t += 256) {
            int c = t >> 4, k4 = t & 15;
            const float* src = qkv + base + (size_t)(jb * 64 + c) * 3072;
            float4 kv = *(const float4*)(src + 64 + k4 * 4);
            KP[(k4 * 4 + 0) * 68 + c] = kv.x;
            KP[(k4 * 4 + 1) * 68 + c] = kv.y;
            KP[(k4 * 4 + 2) * 68 + c] = kv.z;
            KP[(k4 * 4 + 3) * 68 + c] = kv.w;
            float4 vv = *(const float4*)(src + 128 + k4 * 4);
            *(float4*)(&Vs[c * 68 + k4 * 4]) = vv;
        }
        __syncthreads();

        // S = (Q/8) @ K^T : 4x4 per thread
        float s[4][4];
#pragma unroll
        for (int i = 0; i < 4; i++)
#pragma unroll
            for (int j = 0; j < 4; j++) s[i][j] = 0.f;

#pragma unroll 8
        for (int k = 0; k < 64; k++) {
            float4 q4 = *(const float4*)(Qs + k * 68 + ty * 4);
            float4 k4v = *(const float4*)(KP + k * 68 + tx * 4);
            float qr[4] = {q4.x, q4.y, q4.z, q4.w};
            float kc[4] = {k4v.x, k4v.y, k4v.z, k4v.w};
#pragma unroll
            for (int i = 0; i < 4; i++)
#pragma unroll
                for (int j = 0; j < 4; j++)
                    s[i][j] = fmaf(qr[i], kc[j], s[i][j]);
        }

        if (jb == qb) {   // diagonal block: mask c > r (within-block offsets equal)
#pragma unroll
            for (int i = 0; i < 4; i++)
#pragma unroll
                for (int j = 0; j < 4; j++)
                    if (tx * 4 + j > ty * 4 + i) s[i][j] = -1.0e30f;
        }

        // Online softmax: rows live in 16-lane shuffle groups (same ty)
#pragma unroll
        for (int i = 0; i < 4; i++) {
            float rm = fmaxf(fmaxf(s[i][0], s[i][1]), fmaxf(s[i][2], s[i][3]));
#pragma unroll
            for (int off = 8; off > 0; off >>= 1)
                rm = fmaxf(rm, __shfl_xor_sync(0xffffffffu, rm, off, 16));
            float mn = fmaxf(m[i], rm);
            float corr = __expf(m[i] - mn);
            m[i] = mn;
            float rs = 0.f;
#pragma unroll
            for (int j = 0; j < 4; j++) { s[i][j] = __expf(s[i][j] - mn); rs += s[i][j]; }
#pragma unroll
            for (int off = 8; off > 0; off >>= 1)
                rs += __shfl_xor_sync(0xffffffffu, rs, off, 16);
            l[i] = l[i] * corr + rs;
#pragma unroll
            for (int j = 0; j < 4; j++) o[i][j] *= corr;
        }

        __syncthreads();   // all K reads done; safe to overwrite with P
#pragma unroll
        for (int i = 0; i < 4; i++)
            *(float4*)(&KP[(ty * 4 + i) * 68 + tx * 4]) =
                make_float4(s[i][0], s[i][1], s[i][2], s[i][3]);
        __syncthreads();   // P visible

        // O += P @ V
#pragma unroll 8
        for (int k = 0; k < 64; k++) {
            float pr[4];
#pragma unroll
            for (int i = 0; i < 4; i++) pr[i] = KP[(ty * 4 + i) * 68 + k];
            float4 v4 = *(const float4*)(Vs + k * 68 + tx * 4);
            float vc[4] = {v4.x, v4.y, v4.z, v4.w};
#pragma unroll
            for (int i = 0; i < 4; i++)
#pragma unroll
                for (int j = 0; j < 4; j++)
                    o[i][j] = fmaf(pr[i], vc[j], o[i][j]);
        }
    }

    // Normalize and write: att is [B][H][S][HD] contiguous (raw-reshape layout)
#pragma unroll
    for (int i = 0; i < 4; i++) {
        float inv = 1.0f / l[i];
        size_t dst = (((size_t)bh * Sq) + (size_t)(qb * 64 + ty * 4 + i)) * 64 + tx * 4;
        *(float4*)(att + dst) =
            make_float4(o[i][0] * inv, o[i][1] * inv, o[i][2] * inv, o[i][3] * inv);
    }
}

// ----------------------------------------------------------------------------
extern "C" void kernel_launch(void* const* d_in, const int* in_sizes, int n_in,
                              void* d_out, int out_size)
{
    (void)in_sizes; (void)n_in; (void)out_size;
    const float* x    = (const float*)d_in[0];
    const float* Wqkv = (const float*)d_in[1];
    const float* bqkv = (const float*)d_in[2];
    const float* Wout = (const float*)d_in[3];
    const float* bout = (const float*)d_in[4];
    // d_in[5] = mask: causal is implicit in flash_attn, unused
    float* out = (float*)d_out;

    float *qkv = nullptr, *att = nullptr;
    cudaGetSymbolAddress((void**)&qkv, g_qkv);
    cudaGetSymbolAddress((void**)&att, g_att);

    // 1) fused QKV projection: [4096,1024] @ [1024,3072] + b_qkv
    sgemm_bias<<<dim3(3072 / 128, 4096 / 128), 256>>>(
        Bsz * Sq, 3 * Dm, Dm, x, Wqkv, bqkv, qkv);

    // 2) causal flash attention -> g_att ([B][H][S][HD] contiguous)
    const int attn_smem = 3 * 64 * 68 * 4;  // 52224 B
    cudaFuncSetAttribute(flash_attn, cudaFuncAttributeMaxDynamicSharedMemorySize, attn_smem);
    flash_attn<<<dim3(Sq / 64, Bsz * Hn), 256, attn_smem>>>(qkv, att);

    // 3) output projection on the raw-reshaped values: [4096,1024] @ [1024,1024] + b_out
    sgemm_bias<<<dim3(Dm / 128, 4096 / 128), 256>>>(
        Bsz * Sq, Dm, Dm, att, Wout, bout, out);
}

// round 5
// speedup vs baseline: 1.3019x; 1.3019x over previous
#include <cuda_runtime.h>
#include <cuda_bf16.h>
#include <math.h>
#include <stdint.h>

// Problem constants
#define Bsz 2
#define Sq  2048
#define Dm  1024
#define Hn  16
#define HDm 64

// ---------------------------------------------------------------------------
// Scratch (__device__ globals; allocation-free rule)
// ---------------------------------------------------------------------------
__device__ float g_qkv[(size_t)Bsz * Sq * 3 * Dm];             // [4096][3072] fp32
__device__ __nv_bfloat16 g_x_hi[(size_t)Bsz * Sq * Dm];        // [4096][1024]
__device__ __nv_bfloat16 g_x_lo[(size_t)Bsz * Sq * Dm];
__device__ __nv_bfloat16 g_wq_hi[(size_t)3 * Dm * Dm];         // [3072][1024] (W_qkv^T)
__device__ __nv_bfloat16 g_wq_lo[(size_t)3 * Dm * Dm];
__device__ __nv_bfloat16 g_wo_hi[(size_t)Dm * Dm];             // [1024][1024] (W_out^T)
__device__ __nv_bfloat16 g_wo_lo[(size_t)Dm * Dm];
__device__ __nv_bfloat16 g_att_hi[(size_t)Bsz * Sq * Dm];      // [4096][1024] raw-reshape
__device__ __nv_bfloat16 g_att_lo[(size_t)Bsz * Sq * Dm];

// ---------------------------------------------------------------------------
// Baseline-PTX helpers (sm_80+ family-stable; assemble on plain sm_103)
// ---------------------------------------------------------------------------
__device__ __forceinline__ uint32_t smem_u32(const void* p) {
    uint32_t a;
    asm("{ .reg .u64 t; cvta.to.shared.u64 t, %1; cvt.u32.u64 %0, t; }" : "=r"(a) : "l"(p));
    return a;
}
__device__ __forceinline__ void cp_async16(uint32_t s, const void* g) {
    asm volatile("cp.async.cg.shared.global [%0], [%1], 16;\n" :: "r"(s), "l"(g));
}
__device__ __forceinline__ void cp_commit() {
    asm volatile("cp.async.commit_group;\n" ::: "memory");
}
__device__ __forceinline__ void cp_wait0() {
    asm volatile("cp.async.wait_group 0;\n" ::: "memory");
}
__device__ __forceinline__ void cp_wait1() {
    asm volatile("cp.async.wait_group 1;\n" ::: "memory");
}
__device__ __forceinline__ void ldm_x4(uint32_t* r, uint32_t addr) {
    asm volatile("ldmatrix.sync.aligned.m8n8.x4.shared.b16 {%0,%1,%2,%3}, [%4];"
                 : "=r"(r[0]), "=r"(r[1]), "=r"(r[2]), "=r"(r[3]) : "r"(addr));
}
__device__ __forceinline__ void mma16816(float* d, const uint32_t* a,
                                         uint32_t b0, uint32_t b1) {
    asm volatile(
        "mma.sync.aligned.m16n8k16.row.col.f32.bf16.bf16.f32 "
        "{%0,%1,%2,%3},{%4,%5,%6,%7},{%8,%9},{%0,%1,%2,%3};"
        : "+f"(d[0]), "+f"(d[1]), "+f"(d[2]), "+f"(d[3])
        : "r"(a[0]), "r"(a[1]), "r"(a[2]), "r"(a[3]), "r"(b0), "r"(b1));
}

// ---------------------------------------------------------------------------
// Conversion kernels: fp32 -> (hi, lo) bf16 split
// ---------------------------------------------------------------------------
__global__ void split_ew(const float* __restrict__ A,
                         __nv_bfloat16* __restrict__ hi, __nv_bfloat16* __restrict__ lo)
{
    int i = blockIdx.x * blockDim.x + threadIdx.x;  // n/4 threads
    float4 v = ((const float4*)A)[i];
    __nv_bfloat16 h0 = __float2bfloat16(v.x), h1 = __float2bfloat16(v.y);
    __nv_bfloat16 h2 = __float2bfloat16(v.z), h3 = __float2bfloat16(v.w);
    __nv_bfloat162* H = (__nv_bfloat162*)hi;
    __nv_bfloat162* L = (__nv_bfloat162*)lo;
    H[2 * i]     = __nv_bfloat162(h0, h1);
    H[2 * i + 1] = __nv_bfloat162(h2, h3);
    L[2 * i]     = __nv_bfloat162(__float2bfloat16(v.x - __bfloat162float(h0)),
                                  __float2bfloat16(v.y - __bfloat162float(h1)));
    L[2 * i + 1] = __nv_bfloat162(__float2bfloat16(v.z - __bfloat162float(h2)),
                                  __float2bfloat16(v.w - __bfloat162float(h3)));
}

// W [K][N] fp32 -> T [N][K] bf16 hi/lo (transposed split)
__global__ void transpose_split(const float* __restrict__ W, int K, int N,
                                __nv_bfloat16* __restrict__ Thi, __nv_bfloat16* __restrict__ Tlo)
{
    __shared__ float t[32][33];
    int n0 = blockIdx.x * 32, k0 = blockIdx.y * 32;
    int tx = threadIdx.x, ty = threadIdx.y;  // 32x8
#pragma unroll
    for (int r = ty; r < 32; r += 8)
        t[r][tx] = W[(size_t)(k0 + r) * N + n0 + tx];
    __syncthreads();
#pragma unroll
    for (int r = ty; r < 32; r += 8) {
        float v = t[tx][r];  // W[k0+tx][n0+r]
        __nv_bfloat16 h = __float2bfloat16(v);
        size_t dst = (size_t)(n0 + r) * K + k0 + tx;
        Thi[dst] = h;
        Tlo[dst] = __float2bfloat16(v - __bfloat162float(h));
    }
}

// ---------------------------------------------------------------------------
// bf16x2-split GEMM via mma.sync: C[M,N] = A @ B^T + bias (fp32-equivalent).
// A: [M][K] hi/lo, B: [N][K] hi/lo. CTA tile 128x128, 8 warps (2m x 4n),
// warp tile 64x32. K-chunk 32, double-buffered cp.async.
// smem tile: 128 rows x 32 bf16, row stride 40 elems (80B) -> conflict-free
// ldmatrix (20r mod 32 cycles all banks over 8 rows).
// ---------------------------------------------------------------------------
#define TILE_B   10240                       // 128 * 80 bytes
#define GEMM_SMEM (2 * 4 * TILE_B)           // 81920

__global__ __launch_bounds__(256, 1) void gemm_mma(
    int M, int N, int K,
    const __nv_bfloat16* __restrict__ Ahi, const __nv_bfloat16* __restrict__ Alo,
    const __nv_bfloat16* __restrict__ Bhi, const __nv_bfloat16* __restrict__ Blo,
    const float* __restrict__ bias, float* __restrict__ C)
{
    extern __shared__ char smc[];
    const uint32_t sb = smem_u32(smc);
    const int tid  = threadIdx.x;
    const int wid  = tid >> 5;
    const int lane = tid & 31;
    const int by = blockIdx.y * 128;
    const int bx = blockIdx.x * 128;
    const int wm = wid & 1;        // 0..1  (64-row band)
    const int wn = wid >> 1;       // 0..3  (32-col band)

    // tile order in each buffer: 0=Ahi 1=Alo 2=Bhi 3=Blo
    auto tile = [&](int buf, int t) -> uint32_t {
        return sb + (uint32_t)(buf * 4 + t) * TILE_B;
    };
    auto load_tile = [&](uint32_t sbase, const __nv_bfloat16* src, int row0, int k0) {
#pragma unroll
        for (int g = tid; g < 512; g += 256) {
            int r = g >> 2, s = g & 3;
            cp_async16(sbase + (uint32_t)(r * 80 + s * 16),
                       (const char*)(src + (size_t)(row0 + r) * K + k0) + s * 16);
        }
    };
    auto load_chunk = [&](int buf, int k0) {
        load_tile(tile(buf, 0), Ahi, by, k0);
        load_tile(tile(buf, 1), Alo, by, k0);
        load_tile(tile(buf, 2), Bhi, bx, k0);
        load_tile(tile(buf, 3), Blo, bx, k0);
        cp_commit();
    };

    float acc[4][4][4];
#pragma unroll
    for (int i = 0; i < 4; i++)
#pragma unroll
        for (int j = 0; j < 4; j++)
#pragma unroll
            for (int k = 0; k < 4; k++) acc[i][j][k] = 0.f;

    const int NC = K / 32;
    load_chunk(0, 0);

    // ldmatrix thread pattern: row = base + (lane&15), k += (lane>>4)*8
    const uint32_t lrow = (uint32_t)(lane & 15);
    const uint32_t lkb  = (uint32_t)((lane >> 4) * 8) * 2;   // byte offset in k

    for (int c = 0; c < NC; c++) {
        const int cur = c & 1;
        if (c + 1 < NC) { load_chunk(cur ^ 1, (c + 1) * 32); cp_wait1(); }
        else            { cp_wait0(); }
        __syncthreads();

        const uint32_t sAh = tile(cur, 0), sAl = tile(cur, 1);
        const uint32_t sBh = tile(cur, 2), sBl = tile(cur, 3);

#pragma unroll
        for (int ks = 0; ks < 2; ks++) {
            const uint32_t kby = (uint32_t)(ks * 16) * 2 + lkb;  // k byte offset
            uint32_t a[4][4], bh0[4], bh1[4], bl0[4], bl1[4];

            // A_hi fragments (4 m-tiles)
#pragma unroll
            for (int mt = 0; mt < 4; mt++)
                ldm_x4(a[mt], sAh + (uint32_t)((wm * 64 + mt * 16) + lrow) * 80 + kby);
            // B_hi / B_lo fragments (2 x 16-n groups = 4 n-tiles)
            ldm_x4(bh0, sBh + (uint32_t)(wn * 32 + lrow) * 80 + kby);
            ldm_x4(bh1, sBh + (uint32_t)(wn * 32 + 16 + lrow) * 80 + kby);
            ldm_x4(bl0, sBl + (uint32_t)(wn * 32 + lrow) * 80 + kby);
            ldm_x4(bl1, sBl + (uint32_t)(wn * 32 + 16 + lrow) * 80 + kby);

            // pass 1: Ahi @ Bhi ; pass 2: Ahi @ Blo
#pragma unroll
            for (int mt = 0; mt < 4; mt++) {
                mma16816(acc[mt][0], a[mt], bh0[0], bh0[2]);
                mma16816(acc[mt][1], a[mt], bh0[1], bh0[3]);
                mma16816(acc[mt][2], a[mt], bh1[0], bh1[2]);
                mma16816(acc[mt][3], a[mt], bh1[1], bh1[3]);
            }
#pragma unroll
            for (int mt = 0; mt < 4; mt++) {
                mma16816(acc[mt][0], a[mt], bl0[0], bl0[2]);
                mma16816(acc[mt][1], a[mt], bl0[1], bl0[3]);
                mma16816(acc[mt][2], a[mt], bl1[0], bl1[2]);
                mma16816(acc[mt][3], a[mt], bl1[1], bl1[3]);
            }
            // pass 3: Alo @ Bhi (reuse A regs)
#pragma unroll
            for (int mt = 0; mt < 4; mt++)
                ldm_x4(a[mt], sAl + (uint32_t)((wm * 64 + mt * 16) + lrow) * 80 + kby);
#pragma unroll
            for (int mt = 0; mt < 4; mt++) {
                mma16816(acc[mt][0], a[mt], bh0[0], bh0[2]);
                mma16816(acc[mt][1], a[mt], bh0[1], bh0[3]);
                mma16816(acc[mt][2], a[mt], bh1[0], bh1[2]);
                mma16816(acc[mt][3], a[mt], bh1[1], bh1[3]);
            }
        }
        __syncthreads();
    }

    // Epilogue: d-frag layout m16n8 -> (row = lane>>2 [+8], col = (lane&3)*2)
    const int r0 = lane >> 2;
    const int c0 = (lane & 3) * 2;
#pragma unroll
    for (int mt = 0; mt < 4; mt++) {
#pragma unroll
        for (int nt = 0; nt < 4; nt++) {
            int row = by + wm * 64 + mt * 16 + r0;
            int col = bx + wn * 32 + nt * 8 + c0;
            float b0 = bias[col], b1 = bias[col + 1];
            float2 v0 = make_float2(acc[mt][nt][0] + b0, acc[mt][nt][1] + b1);
            float2 v1 = make_float2(acc[mt][nt][2] + b0, acc[mt][nt][3] + b1);
            *(float2*)(C + (size_t)row * N + col) = v0;
            *(float2*)(C + (size_t)(row + 8) * N + col) = v1;
        }
    }
}

// ---------------------------------------------------------------------------
// Flash attention (fp32, causal); epilogue emits bf16 hi/lo at raw-reshape
// layout [B][H][S][HD] (faithful to reference's reshape-without-transpose).
// ---------------------------------------------------------------------------
__global__ __launch_bounds__(256) void flash_attn(
    const float* __restrict__ qkv,
    __nv_bfloat16* __restrict__ att_hi, __nv_bfloat16* __restrict__ att_lo)
{
    extern __shared__ float sm[];
    float* Qs = sm;                  // [hd][row], stride 68, pre-scaled by 1/8
    float* KP = sm + 64 * 68;        // K: [hd][col] ; P: [row][kv]
    float* Vs = sm + 2 * 64 * 68;    // [kv][hd]

    const int bh = blockIdx.y;
    const int b  = bh >> 4;
    const int h  = bh & 15;
    const int qb = blockIdx.x;
    const int tid = threadIdx.x;
    const int tx = tid & 15;
    const int ty = tid >> 4;

    const size_t base = (size_t)b * Sq * 3072 + (size_t)h * 192;

#pragma unroll
    for (int t = tid; t < 1024; t += 256) {
        int r = t >> 4, k4 = t & 15;
        float4 v = *(const float4*)(qkv + base + (size_t)(qb * 64 + r) * 3072 + k4 * 4);
        Qs[(k4 * 4 + 0) * 68 + r] = v.x * 0.125f;
        Qs[(k4 * 4 + 1) * 68 + r] = v.y * 0.125f;
        Qs[(k4 * 4 + 2) * 68 + r] = v.z * 0.125f;
        Qs[(k4 * 4 + 3) * 68 + r] = v.w * 0.125f;
    }

    float m[4], l[4], o[4][4];
#pragma unroll
    for (int i = 0; i < 4; i++) {
        m[i] = -3.0e38f; l[i] = 0.f;
#pragma unroll
        for (int j = 0; j < 4; j++) o[i][j] = 0.f;
    }

    for (int jb = 0; jb <= qb; jb++) {
        __syncthreads();
#pragma unroll
        for (int t = tid; t < 1024; t += 256) {
            int c = t >> 4, k4 = t & 15;
            const float* src = qkv + base + (size_t)(jb * 64 + c) * 3072;
            float4 kv = *(const float4*)(src + 64 + k4 * 4);
            KP[(k4 * 4 + 0) * 68 + c] = kv.x;
            KP[(k4 * 4 + 1) * 68 + c] = kv.y;
            KP[(k4 * 4 + 2) * 68 + c] = kv.z;
            KP[(k4 * 4 + 3) * 68 + c] = kv.w;
            float4 vv = *(const float4*)(src + 128 + k4 * 4);
            *(float4*)(&Vs[c * 68 + k4 * 4]) = vv;
        }
        __syncthreads();

        float s[4][4];
#pragma unroll
        for (int i = 0; i < 4; i++)
#pragma unroll
            for (int j = 0; j < 4; j++) s[i][j] = 0.f;

#pragma unroll 8
        for (int k = 0; k < 64; k++) {
            float4 q4 = *(const float4*)(Qs + k * 68 + ty * 4);
            float4 k4v = *(const float4*)(KP + k * 68 + tx * 4);
            float qr[4] = {q4.x, q4.y, q4.z, q4.w};
            float kc[4] = {k4v.x, k4v.y, k4v.z, k4v.w};
#pragma unroll
            for (int i = 0; i < 4; i++)
#pragma unroll
                for (int j = 0; j < 4; j++)
                    s[i][j] = fmaf(qr[i], kc[j], s[i][j]);
        }

        if (jb == qb) {
#pragma unroll
            for (int i = 0; i < 4; i++)
#pragma unroll
                for (int j = 0; j < 4; j++)
                    if (tx * 4 + j > ty * 4 + i) s[i][j] = -1.0e30f;
        }

#pragma unroll
        for (int i = 0; i < 4; i++) {
            float rm = fmaxf(fmaxf(s[i][0], s[i][1]), fmaxf(s[i][2], s[i][3]));
#pragma unroll
            for (int off = 8; off > 0; off >>= 1)
                rm = fmaxf(rm, __shfl_xor_sync(0xffffffffu, rm, off, 16));
            float mn = fmaxf(m[i], rm);
            float corr = __expf(m[i] - mn);
            m[i] = mn;
            float rs = 0.f;
#pragma unroll
            for (int j = 0; j < 4; j++) { s[i][j] = __expf(s[i][j] - mn); rs += s[i][j]; }
#pragma unroll
            for (int off = 8; off > 0; off >>= 1)
                rs += __shfl_xor_sync(0xffffffffu, rs, off, 16);
            l[i] = l[i] * corr + rs;
#pragma unroll
            for (int j = 0; j < 4; j++) o[i][j] *= corr;
        }

        __syncthreads();
#pragma unroll
        for (int i = 0; i < 4; i++)
            *(float4*)(&KP[(ty * 4 + i) * 68 + tx * 4]) =
                make_float4(s[i][0], s[i][1], s[i][2], s[i][3]);
        __syncthreads();

#pragma unroll 8
        for (int k = 0; k < 64; k++) {
            float pr[4];
#pragma unroll
            for (int i = 0; i < 4; i++) pr[i] = KP[(ty * 4 + i) * 68 + k];
            float4 v4 = *(const float4*)(Vs + k * 68 + tx * 4);
            float vc[4] = {v4.x, v4.y, v4.z, v4.w};
#pragma unroll
            for (int i = 0; i < 4; i++)
#pragma unroll
                for (int j = 0; j < 4; j++)
                    o[i][j] = fmaf(pr[i], vc[j], o[i][j]);
        }
    }

#pragma unroll
    for (int i = 0; i < 4; i++) {
        float inv = 1.0f / l[i];
        size_t dst = (((size_t)bh * Sq) + (size_t)(qb * 64 + ty * 4 + i)) * 64 + tx * 4;
        float r0 = o[i][0] * inv, r1 = o[i][1] * inv, r2 = o[i][2] * inv, r3 = o[i][3] * inv;
        __nv_bfloat16 h0 = __float2bfloat16(r0), h1 = __float2bfloat16(r1);
        __nv_bfloat16 h2 = __float2bfloat16(r2), h3 = __float2bfloat16(r3);
        ((__nv_bfloat162*)(att_hi + dst))[0] = __nv_bfloat162(h0, h1);
        ((__nv_bfloat162*)(att_hi + dst))[1] = __nv_bfloat162(h2, h3);
        ((__nv_bfloat162*)(att_lo + dst))[0] =
            __nv_bfloat162(__float2bfloat16(r0 - __bfloat162float(h0)),
                           __float2bfloat16(r1 - __bfloat162float(h1)));
        ((__nv_bfloat162*)(att_lo + dst))[1] =
            __nv_bfloat162(__float2bfloat16(r2 - __bfloat162float(h2)),
                           __float2bfloat16(r3 - __bfloat162float(h3)));
    }
}

// ---------------------------------------------------------------------------
extern "C" void kernel_launch(void* const* d_in, const int* in_sizes, int n_in,
                              void* d_out, int out_size)
{
    (void)in_sizes; (void)n_in; (void)out_size;
    const float* x    = (const float*)d_in[0];
    const float* Wqkv = (const float*)d_in[1];
    const float* bqkv = (const float*)d_in[2];
    const float* Wout = (const float*)d_in[3];
    const float* bout = (const float*)d_in[4];
    float* out = (float*)d_out;

    float *qkv;
    __nv_bfloat16 *xh, *xl, *wqh, *wql, *woh, *wol, *ah, *al;
    cudaGetSymbolAddress((void**)&qkv, g_qkv);
    cudaGetSymbolAddress((void**)&xh, g_x_hi);
    cudaGetSymbolAddress((void**)&xl, g_x_lo);
    cudaGetSymbolAddress((void**)&wqh, g_wq_hi);
    cudaGetSymbolAddress((void**)&wql, g_wq_lo);
    cudaGetSymbolAddress((void**)&woh, g_wo_hi);
    cudaGetSymbolAddress((void**)&wol, g_wo_lo);
    cudaGetSymbolAddress((void**)&ah, g_att_hi);
    cudaGetSymbolAddress((void**)&al, g_att_lo);

    // Splits / transposed splits
    split_ew<<<(Bsz * Sq * Dm / 4) / 256, 256>>>(x, xh, xl);
    transpose_split<<<dim3(3 * Dm / 32, Dm / 32), dim3(32, 8)>>>(Wqkv, Dm, 3 * Dm, wqh, wql);
    transpose_split<<<dim3(Dm / 32, Dm / 32), dim3(32, 8)>>>(Wout, Dm, Dm, woh, wol);

    cudaFuncSetAttribute(gemm_mma, cudaFuncAttributeMaxDynamicSharedMemorySize, GEMM_SMEM);

    // 1) QKV projection: [4096,3072] = x @ W_qkv + b
    gemm_mma<<<dim3(3 * Dm / 128, Bsz * Sq / 128), 256, GEMM_SMEM>>>(
        Bsz * Sq, 3 * Dm, Dm, xh, xl, wqh, wql, bqkv, qkv);

    // 2) causal flash attention -> att hi/lo bf16
    const int attn_smem = 3 * 64 * 68 * 4;
    cudaFuncSetAttribute(flash_attn, cudaFuncAttributeMaxDynamicSharedMemorySize, attn_smem);
    flash_attn<<<dim3(Sq / 64, Bsz * Hn), 256, attn_smem>>>(qkv, ah, al);

    // 3) output projection: [4096,1024] = att @ W_out + b
    gemm_mma<<<dim3(Dm / 128, Bsz * Sq / 128), 256, GEMM_SMEM>>>(
        Bsz * Sq, Dm, Dm, ah, al, woh, wol, bout, out);
}

// round 8
// speedup vs baseline: 1.4550x; 1.1176x over previous
#include <cuda_runtime.h>
#include <cuda_bf16.h>
#include <math.h>
#include <stdint.h>

// Problem constants
#define Bsz 2
#define Sq  2048
#define Dm  1024
#define Hn  16
#define HDm 64

// ---------------------------------------------------------------------------
// Scratch (__device__ globals; allocation-free rule)
// Head-major layouts: [B*H][S][HD] bf16 hi/lo
// ---------------------------------------------------------------------------
#define HEADELEMS ((size_t)Bsz * Hn * Sq * HDm)   // 4M elems = 8MB bf16
__device__ __nv_bfloat16 g_q_hi[HEADELEMS];
__device__ __nv_bfloat16 g_q_lo[HEADELEMS];
__device__ __nv_bfloat16 g_k_hi[HEADELEMS];
__device__ __nv_bfloat16 g_k_lo[HEADELEMS];
__device__ __nv_bfloat16 g_v_hi[HEADELEMS];
__device__ __nv_bfloat16 g_v_lo[HEADELEMS];
__device__ __nv_bfloat16 g_att_hi[HEADELEMS];     // raw-reshape layout
__device__ __nv_bfloat16 g_att_lo[HEADELEMS];
__device__ __nv_bfloat16 g_x_hi[(size_t)Bsz * Sq * Dm];
__device__ __nv_bfloat16 g_x_lo[(size_t)Bsz * Sq * Dm];
__device__ __nv_bfloat16 g_wq_hi[(size_t)3 * Dm * Dm];   // W_qkv^T [3072][1024]
__device__ __nv_bfloat16 g_wq_lo[(size_t)3 * Dm * Dm];
__device__ __nv_bfloat16 g_wo_hi[(size_t)Dm * Dm];       // W_out^T [1024][1024]
__device__ __nv_bfloat16 g_wo_lo[(size_t)Dm * Dm];

// ---------------------------------------------------------------------------
// Baseline-PTX helpers (sm_80+ family-stable; assemble on plain sm_103)
// ---------------------------------------------------------------------------
__device__ __forceinline__ uint32_t smem_u32(const void* p) {
    uint32_t a;
    asm("{ .reg .u64 t; cvta.to.shared.u64 t, %1; cvt.u32.u64 %0, t; }" : "=r"(a) : "l"(p));
    return a;
}
__device__ __forceinline__ void cp_async16(uint32_t s, const void* g) {
    asm volatile("cp.async.cg.shared.global [%0], [%1], 16;\n" :: "r"(s), "l"(g));
}
__device__ __forceinline__ void cp_commit() {
    asm volatile("cp.async.commit_group;\n" ::: "memory");
}
__device__ __forceinline__ void cp_wait0() {
    asm volatile("cp.async.wait_group 0;\n" ::: "memory");
}
__device__ __forceinline__ void cp_wait1() {
    asm volatile("cp.async.wait_group 1;\n" ::: "memory");
}
__device__ __forceinline__ void ldm_x4(uint32_t* r, uint32_t addr) {
    asm volatile("ldmatrix.sync.aligned.m8n8.x4.shared.b16 {%0,%1,%2,%3}, [%4];"
                 : "=r"(r[0]), "=r"(r[1]), "=r"(r[2]), "=r"(r[3]) : "r"(addr));
}
__device__ __forceinline__ void ldm_x4_t(uint32_t* r, uint32_t addr) {
    asm volatile("ldmatrix.sync.aligned.m8n8.x4.trans.shared.b16 {%0,%1,%2,%3}, [%4];"
                 : "=r"(r[0]), "=r"(r[1]), "=r"(r[2]), "=r"(r[3]) : "r"(addr));
}
__device__ __forceinline__ void mma16816(float* d, const uint32_t* a,
                                         uint32_t b0, uint32_t b1) {
    asm volatile(
        "mma.sync.aligned.m16n8k16.row.col.f32.bf16.bf16.f32 "
        "{%0,%1,%2,%3},{%4,%5,%6,%7},{%8,%9},{%0,%1,%2,%3};"
        : "+f"(d[0]), "+f"(d[1]), "+f"(d[2]), "+f"(d[3])
        : "r"(a[0]), "r"(a[1]), "r"(a[2]), "r"(a[3]), "r"(b0), "r"(b1));
}
__device__ __forceinline__ uint32_t pack_bf2(float a, float b) {
    __nv_bfloat162 h = __floats2bfloat162_rn(a, b);
    return *(uint32_t*)&h;
}

// ---------------------------------------------------------------------------
// Conversion kernels: fp32 -> (hi, lo) bf16 split
// ---------------------------------------------------------------------------
__global__ void split_ew(const float* __restrict__ A,
                         __nv_bfloat16* __restrict__ hi, __nv_bfloat16* __restrict__ lo)
{
    int i = blockIdx.x * blockDim.x + threadIdx.x;
    float4 v = ((const float4*)A)[i];
    __nv_bfloat16 h0 = __float2bfloat16(v.x), h1 = __float2bfloat16(v.y);
    __nv_bfloat16 h2 = __float2bfloat16(v.z), h3 = __float2bfloat16(v.w);
    __nv_bfloat162* H = (__nv_bfloat162*)hi;
    __nv_bfloat162* L = (__nv_bfloat162*)lo;
    H[2 * i]     = __nv_bfloat162(h0, h1);
    H[2 * i + 1] = __nv_bfloat162(h2, h3);
    L[2 * i]     = __nv_bfloat162(__float2bfloat16(v.x - __bfloat162float(h0)),
                                  __float2bfloat16(v.y - __bfloat162float(h1)));
    L[2 * i + 1] = __nv_bfloat162(__float2bfloat16(v.z - __bfloat162float(h2)),
                                  __float2bfloat16(v.w - __bfloat162float(h3)));
}

// W [K][N] fp32 -> T [N][K] bf16 hi/lo (transposed split)
__global__ void transpose_split(const float* __restrict__ W, int K, int N,
                                __nv_bfloat16* __restrict__ Thi, __nv_bfloat16* __restrict__ Tlo)
{
    __shared__ float t[32][33];
    int n0 = blockIdx.x * 32, k0 = blockIdx.y * 32;
    int tx = threadIdx.x, ty = threadIdx.y;  // 32x8
#pragma unroll
    for (int r = ty; r < 32; r += 8)
        t[r][tx] = W[(size_t)(k0 + r) * N + n0 + tx];
    __syncthreads();
#pragma unroll
    for (int r = ty; r < 32; r += 8) {
        float v = t[tx][r];
        __nv_bfloat16 h = __float2bfloat16(v);
        size_t dst = (size_t)(n0 + r) * K + k0 + tx;
        Thi[dst] = h;
        Tlo[dst] = __float2bfloat16(v - __bfloat162float(h));
    }
}

// ---------------------------------------------------------------------------
// bf16x2-split GEMM via mma.sync, 512 threads, 16 warps (4m x 4n), warp tile
// 32x32. CTA tile 128x128, K-chunk 32, double-buffered cp.async.
// mode 0: C = A@B^T + bias (fp32 out).
// mode 1: QKV epilogue -> scatter bf16 hi/lo into head-major Q/K/V arrays.
// ---------------------------------------------------------------------------
#define TILE_B   10240                       // 128 rows * 80 bytes
#define GEMM_SMEM (2 * 4 * TILE_B)           // 81920

__global__ __launch_bounds__(512, 1) void gemm512(
    int M, int N, int K,
    const __nv_bfloat16* __restrict__ Ahi, const __nv_bfloat16* __restrict__ Alo,
    const __nv_bfloat16* __restrict__ Bhi, const __nv_bfloat16* __restrict__ Blo,
    const float* __restrict__ bias, float* __restrict__ C, int mode,
    __nv_bfloat16* __restrict__ qh, __nv_bfloat16* __restrict__ ql,
    __nv_bfloat16* __restrict__ kh, __nv_bfloat16* __restrict__ kl,
    __nv_bfloat16* __restrict__ vh, __nv_bfloat16* __restrict__ vl)
{
    extern __shared__ char smc[];
    const uint32_t sb = smem_u32(smc);
    const int tid  = threadIdx.x;
    const int wid  = tid >> 5;
    const int lane = tid & 31;
    const int by = blockIdx.y * 128;
    const int bx = blockIdx.x * 128;
    const int wm = wid & 3;        // 0..3  (32-row band)
    const int wn = wid >> 2;       // 0..3  (32-col band)

    auto tile = [&](int buf, int t) -> uint32_t {
        return sb + (uint32_t)(buf * 4 + t) * TILE_B;
    };
    auto load_tile = [&](uint32_t sbase, const __nv_bfloat16* src, int row0, int k0) {
        int r = tid >> 2, s = tid & 3;   // 512 threads -> one 16B chunk each
        cp_async16(sbase + (uint32_t)(r * 80 + s * 16),
                   (const char*)(src + (size_t)(row0 + r) * K + k0) + s * 16);
    };
    auto load_chunk = [&](int buf, int k0) {
        load_tile(tile(buf, 0), Ahi, by, k0);
        load_tile(tile(buf, 1), Alo, by, k0);
        load_tile(tile(buf, 2), Bhi, bx, k0);
        load_tile(tile(buf, 3), Blo, bx, k0);
        cp_commit();
    };

    float acc[2][4][4];
#pragma unroll
    for (int i = 0; i < 2; i++)
#pragma unroll
        for (int j = 0; j < 4; j++)
#pragma unroll
            for (int k = 0; k < 4; k++) acc[i][j][k] = 0.f;

    const int NC = K / 32;
    load_chunk(0, 0);

    const uint32_t lrow = (uint32_t)(lane & 15);
    const uint32_t lkb  = (uint32_t)((lane >> 4) * 8) * 2;

    for (int c = 0; c < NC; c++) {
        const int cur = c & 1;
        if (c + 1 < NC) { load_chunk(cur ^ 1, (c + 1) * 32); cp_wait1(); }
        else            { cp_wait0(); }
        __syncthreads();

        const uint32_t sAh = tile(cur, 0), sAl = tile(cur, 1);
        const uint32_t sBh = tile(cur, 2), sBl = tile(cur, 3);

#pragma unroll
        for (int ks = 0; ks < 2; ks++) {
            const uint32_t kby = (uint32_t)(ks * 16) * 2 + lkb;
            uint32_t a[2][4], a2[2][4], b[2][4];

#pragma unroll
            for (int mt = 0; mt < 2; mt++) {
                ldm_x4(a[mt],  sAh + (uint32_t)((wm * 32 + mt * 16) + lrow) * 80 + kby);
                ldm_x4(a2[mt], sAl + (uint32_t)((wm * 32 + mt * 16) + lrow) * 80 + kby);
            }
#pragma unroll
            for (int ng = 0; ng < 2; ng++)
                ldm_x4(b[ng], sBh + (uint32_t)((wn * 32 + ng * 16) + lrow) * 80 + kby);

            // Ahi@Bhi, Alo@Bhi
#pragma unroll
            for (int mt = 0; mt < 2; mt++)
#pragma unroll
                for (int ng = 0; ng < 2; ng++) {
                    mma16816(acc[mt][2 * ng + 0], a[mt],  b[ng][0], b[ng][2]);
                    mma16816(acc[mt][2 * ng + 1], a[mt],  b[ng][1], b[ng][3]);
                    mma16816(acc[mt][2 * ng + 0], a2[mt], b[ng][0], b[ng][2]);
                    mma16816(acc[mt][2 * ng + 1], a2[mt], b[ng][1], b[ng][3]);
                }
            // Ahi@Blo
#pragma unroll
            for (int ng = 0; ng < 2; ng++)
                ldm_x4(b[ng], sBl + (uint32_t)((wn * 32 + ng * 16) + lrow) * 80 + kby);
#pragma unroll
            for (int mt = 0; mt < 2; mt++)
#pragma unroll
                for (int ng = 0; ng < 2; ng++) {
                    mma16816(acc[mt][2 * ng + 0], a[mt], b[ng][0], b[ng][2]);
                    mma16816(acc[mt][2 * ng + 1], a[mt], b[ng][1], b[ng][3]);
                }
        }
        __syncthreads();
    }

    const int r0 = lane >> 2;
    const int c0 = (lane & 3) * 2;

    if (mode == 0) {
#pragma unroll
        for (int mt = 0; mt < 2; mt++) {
#pragma unroll
            for (int nt = 0; nt < 4; nt++) {
                int row = by + wm * 32 + mt * 16 + r0;
                int col = bx + wn * 32 + nt * 8 + c0;
                float b0 = bias[col], b1 = bias[col + 1];
                *(float2*)(C + (size_t)row * N + col) =
                    make_float2(acc[mt][nt][0] + b0, acc[mt][nt][1] + b1);
                *(float2*)(C + (size_t)(row + 8) * N + col) =
                    make_float2(acc[mt][nt][2] + b0, acc[mt][nt][3] + b1);
            }
        }
    } else {
        // scatter to head-major Q/K/V hi/lo. col0 is 32-aligned; 192- and
        // 64-blocks are 32-multiples, so h and type are warp-uniform.
        int col0 = bx + wn * 32;
        int h = col0 / 192;
        int t = (col0 % 192) / 64;
        int hdb = col0 & 63;
        __nv_bfloat16* dh = (t == 0) ? qh : (t == 1) ? kh : vh;
        __nv_bfloat16* dl = (t == 0) ? ql : (t == 1) ? kl : vl;
#pragma unroll
        for (int mt = 0; mt < 2; mt++) {
#pragma unroll
            for (int nt = 0; nt < 4; nt++) {
                int gr = by + wm * 32 + mt * 16 + r0;
                int bb = gr >> 11, s = gr & 2047;
                int hd = hdb + nt * 8 + c0;
                int col = col0 + nt * 8 + c0;
                float b0 = bias[col], b1 = bias[col + 1];
                size_t d0 = (((size_t)(bb * Hn + h)) * Sq + s) * HDm + hd;
                size_t d1 = d0 + 8 * HDm;
#pragma unroll
                for (int rr = 0; rr < 2; rr++) {
                    float v0 = acc[mt][nt][2 * rr + 0] + b0;
                    float v1 = acc[mt][nt][2 * rr + 1] + b1;
                    __nv_bfloat162 hh = __floats2bfloat162_rn(v0, v1);
                    __nv_bfloat162 ll = __floats2bfloat162_rn(
                        v0 - __bfloat162float(hh.x), v1 - __bfloat162float(hh.y));
                    size_t d = rr ? d1 : d0;
                    *(__nv_bfloat162*)(dh + d) = hh;
                    *(__nv_bfloat162*)(dl + d) = ll;
                }
            }
        }
    }
}

// ---------------------------------------------------------------------------
// Flash attention via mma.sync bf16 hi/lo (3-pass), causal, online softmax.
// CTA = 128 threads (4 warps), 64 q rows; each warp owns 16 rows x 64 kv.
// smem: Q hi/lo [64][72] + double-buffered K/V hi/lo [64][72] tiles.
// Output: bf16 hi/lo at raw-reshape layout [B*H][S][HD].
// ---------------------------------------------------------------------------
#define FTILE 9216                    // 64 * 72 * 2 bytes
#define FLASH_SMEM (2 * FTILE + 2 * 4 * FTILE)   // 92160

__global__ __launch_bounds__(128, 1) void flash_mma(
    const __nv_bfloat16* __restrict__ qh, const __nv_bfloat16* __restrict__ ql,
    const __nv_bfloat16* __restrict__ kh, const __nv_bfloat16* __restrict__ kl,
    const __nv_bfloat16* __restrict__ vh, const __nv_bfloat16* __restrict__ vl,
    __nv_bfloat16* __restrict__ ah, __nv_bfloat16* __restrict__ al)
{
    extern __shared__ char smc[];
    const uint32_t sb = smem_u32(smc);
    const int tid  = threadIdx.x;
    const int wid  = tid >> 5;
    const int lane = tid & 31;
    const int bh = blockIdx.y;
    const int qb = blockIdx.x;

    const uint32_t sQh = sb, sQl = sb + FTILE;
    auto kvtile = [&](int buf, int t) -> uint32_t {
        return sb + 2 * FTILE + (uint32_t)(buf * 4 + t) * FTILE;
    };

    const char* hb_q  = (const char*)(qh + (size_t)bh * Sq * HDm);
    const char* hb_ql = (const char*)(ql + (size_t)bh * Sq * HDm);
    const char* hb_k  = (const char*)(kh + (size_t)bh * Sq * HDm);
    const char* hb_kl = (const char*)(kl + (size_t)bh * Sq * HDm);
    const char* hb_v  = (const char*)(vh + (size_t)bh * Sq * HDm);
    const char* hb_vl = (const char*)(vl + (size_t)bh * Sq * HDm);

    // tile loader: 64 rows x 128B (8 chunks) = 512 chunks / 128 threads
    auto load_tile = [&](uint32_t dst, const char* srcbase, int row0) {
#pragma unroll
        for (int g = tid; g < 512; g += 128) {
            int r = g >> 3, ch = g & 7;
            cp_async16(dst + (uint32_t)(r * 144 + ch * 16),
                       srcbase + (size_t)(row0 + r) * 128 + ch * 16);
        }
    };
    auto load_kv = [&](int buf, int jb) {
        load_tile(kvtile(buf, 0), hb_k,  jb * 64);
        load_tile(kvtile(buf, 1), hb_kl, jb * 64);
        load_tile(kvtile(buf, 2), hb_v,  jb * 64);
        load_tile(kvtile(buf, 3), hb_vl, jb * 64);
        cp_commit();
    };

    // Q + first KV block in one group
    load_tile(sQh, hb_q,  qb * 64);
    load_tile(sQl, hb_ql, qb * 64);
    load_kv(0, 0);

    float o[8][4];
#pragma unroll
    for (int t = 0; t < 8; t++)
#pragma unroll
        for (int j = 0; j < 4; j++) o[t][j] = 0.f;
    float m0 = -1e30f, m1 = -1e30f, l0 = 0.f, l1 = 0.f;

    const uint32_t lrow = (uint32_t)(lane & 15);
    const uint32_t lkb  = (uint32_t)((lane >> 4) * 16);   // 8 elems * 2B
    const uint32_t qoff = (uint32_t)(wid * 16 + (lane & 15)) * 144 + lkb;
    const int rloc0 = wid * 16 + (lane >> 2);
    const int cpair = (lane & 3) * 2;
    const float scale = 0.125f;   // 1/sqrt(64)

    for (int jb = 0; jb <= qb; jb++) {
        const int buf = jb & 1;
        if (jb + 1 <= qb) { load_kv(buf ^ 1, jb + 1); cp_wait1(); }
        else              { cp_wait0(); }
        __syncthreads();

        const uint32_t sKh = kvtile(buf, 0), sKl = kvtile(buf, 1);
        const uint32_t sVh = kvtile(buf, 2), sVl = kvtile(buf, 3);

        // ----- S = Q @ K^T (3-pass hi/lo) -----
        float s[8][4];
#pragma unroll
        for (int t = 0; t < 8; t++)
#pragma unroll
            for (int j = 0; j < 4; j++) s[t][j] = 0.f;

#pragma unroll
        for (int kc = 0; kc < 4; kc++) {
            const uint32_t kof = (uint32_t)(kc * 32);
            uint32_t a[4], a2[4], b[4][4];
            ldm_x4(a,  sQh + qoff + kof);
            ldm_x4(a2, sQl + qoff + kof);
#pragma unroll
            for (int g = 0; g < 4; g++)
                ldm_x4(b[g], sKh + (uint32_t)(g * 16 + (int)lrow) * 144 + lkb + kof);
#pragma unroll
            for (int g = 0; g < 4; g++) {
                mma16816(s[2 * g + 0], a,  b[g][0], b[g][2]);
                mma16816(s[2 * g + 1], a,  b[g][1], b[g][3]);
                mma16816(s[2 * g + 0], a2, b[g][0], b[g][2]);
                mma16816(s[2 * g + 1], a2, b[g][1], b[g][3]);
            }
#pragma unroll
            for (int g = 0; g < 4; g++)
                ldm_x4(b[g], sKl + (uint32_t)(g * 16 + (int)lrow) * 144 + lkb + kof);
#pragma unroll
            for (int g = 0; g < 4; g++) {
                mma16816(s[2 * g + 0], a, b[g][0], b[g][2]);
                mma16816(s[2 * g + 1], a, b[g][1], b[g][3]);
            }
        }

        // scale + causal mask (diagonal block only)
        if (jb == qb) {
#pragma unroll
            for (int t = 0; t < 8; t++) {
                int c = 8 * t + cpair;
#pragma unroll
                for (int j = 0; j < 4; j++) {
                    int cc = c + (j & 1);
                    int rr = rloc0 + (j >> 1) * 8;
                    s[t][j] = (cc > rr) ? -1e30f : s[t][j] * scale;
                }
            }
        } else {
#pragma unroll
            for (int t = 0; t < 8; t++)
#pragma unroll
                for (int j = 0; j < 4; j++) s[t][j] *= scale;
        }

        // ----- online softmax (rows r0, r1 per thread; quad holds a row) -----
        float rm0 = -1e30f, rm1 = -1e30f;
#pragma unroll
        for (int t = 0; t < 8; t++) {
            rm0 = fmaxf(rm0, fmaxf(s[t][0], s[t][1]));
            rm1 = fmaxf(rm1, fmaxf(s[t][2], s[t][3]));
        }
        rm0 = fmaxf(rm0, __shfl_xor_sync(0xffffffffu, rm0, 1, 4));
        rm0 = fmaxf(rm0, __shfl_xor_sync(0xffffffffu, rm0, 2, 4));
        rm1 = fmaxf(rm1, __shfl_xor_sync(0xffffffffu, rm1, 1, 4));
        rm1 = fmaxf(rm1, __shfl_xor_sync(0xffffffffu, rm1, 2, 4));

        float mn0 = fmaxf(m0, rm0), mn1 = fmaxf(m1, rm1);
        float corr0 = __expf(m0 - mn0), corr1 = __expf(m1 - mn1);
        m0 = mn0; m1 = mn1;

        float rs0 = 0.f, rs1 = 0.f;
#pragma unroll
        for (int t = 0; t < 8; t++) {
            s[t][0] = __expf(s[t][0] - mn0); rs0 += s[t][0];
            s[t][1] = __expf(s[t][1] - mn0); rs0 += s[t][1];
            s[t][2] = __expf(s[t][2] - mn1); rs1 += s[t][2];
            s[t][3] = __expf(s[t][3] - mn1); rs1 += s[t][3];
        }
        rs0 += __shfl_xor_sync(0xffffffffu, rs0, 1, 4);
        rs0 += __shfl_xor_sync(0xffffffffu, rs0, 2, 4);
        rs1 += __shfl_xor_sync(0xffffffffu, rs1, 1, 4);
        rs1 += __shfl_xor_sync(0xffffffffu, rs1, 2, 4);
        l0 = l0 * corr0 + rs0;
        l1 = l1 * corr1 + rs1;
#pragma unroll
        for (int t = 0; t < 8; t++) {
            o[t][0] *= corr0; o[t][1] *= corr0;
            o[t][2] *= corr1; o[t][3] *= corr1;
        }

        // ----- P -> bf16 hi/lo A-fragments -----
        uint32_t ph[8][2], pl[8][2];
#pragma unroll
        for (int t = 0; t < 8; t++) {
            __nv_bfloat162 h0 = __floats2bfloat162_rn(s[t][0], s[t][1]);
            __nv_bfloat162 h1 = __floats2bfloat162_rn(s[t][2], s[t][3]);
            ph[t][0] = *(uint32_t*)&h0;
            ph[t][1] = *(uint32_t*)&h1;
            pl[t][0] = pack_bf2(s[t][0] - __bfloat162float(h0.x),
                                s[t][1] - __bfloat162float(h0.y));
            pl[t][1] = pack_bf2(s[t][2] - __bfloat162float(h1.x),
                                s[t][3] - __bfloat162float(h1.y));
        }

        // ----- O += P @ V (3-pass) -----
        const uint32_t vrow = (uint32_t)(lane & 15) * 144;
        const uint32_t vhd  = (uint32_t)((lane >> 4) * 8) * 2;
#pragma unroll
        for (int kc = 0; kc < 4; kc++) {
            uint32_t a[4]  = {ph[2 * kc][0], ph[2 * kc][1], ph[2 * kc + 1][0], ph[2 * kc + 1][1]};
            uint32_t a2[4] = {pl[2 * kc][0], pl[2 * kc][1], pl[2 * kc + 1][0], pl[2 * kc + 1][1]};
            const uint32_t rb = (uint32_t)(kc * 16) * 144;
#pragma unroll
            for (int hg = 0; hg < 4; hg++) {
                uint32_t bv[4];
                ldm_x4_t(bv, sVh + rb + vrow + (uint32_t)(hg * 16) * 2 + vhd);
                mma16816(o[2 * hg + 0], a,  bv[0], bv[1]);
                mma16816(o[2 * hg + 1], a,  bv[2], bv[3]);
                mma16816(o[2 * hg + 0], a2, bv[0], bv[1]);
                mma16816(o[2 * hg + 1], a2, bv[2], bv[3]);
                ldm_x4_t(bv, sVl + rb + vrow + (uint32_t)(hg * 16) * 2 + vhd);
                mma16816(o[2 * hg + 0], a, bv[0], bv[1]);
                mma16816(o[2 * hg + 1], a, bv[2], bv[3]);
            }
        }
        __syncthreads();   // all smem reads done before next prefetch overwrites
    }

    // ----- epilogue: normalize, hi/lo split, store -----
    const float inv0 = 1.0f / l0, inv1 = 1.0f / l1;
    const size_t rb0 = ((size_t)bh * Sq + (size_t)(qb * 64 + rloc0)) * HDm;
    const size_t rb1 = rb0 + 8 * HDm;
#pragma unroll
    for (int t = 0; t < 8; t++) {
        int hd = 8 * t + cpair;
        float v0 = o[t][0] * inv0, v1 = o[t][1] * inv0;
        float v2 = o[t][2] * inv1, v3 = o[t][3] * inv1;
        __nv_bfloat162 h0 = __floats2bfloat162_rn(v0, v1);
        __nv_bfloat162 h1 = __floats2bfloat162_rn(v2, v3);
        *(__nv_bfloat162*)(ah + rb0 + hd) = h0;
        *(__nv_bfloat162*)(ah + rb1 + hd) = h1;
        *(__nv_bfloat162*)(al + rb0 + hd) = __floats2bfloat162_rn(
            v0 - __bfloat162float(h0.x), v1 - __bfloat162float(h0.y));
        *(__nv_bfloat162*)(al + rb1 + hd) = __floats2bfloat162_rn(
            v2 - __bfloat162float(h1.x), v3 - __bfloat162float(h1.y));
    }
}

// ---------------------------------------------------------------------------
extern "C" void kernel_launch(void* const* d_in, const int* in_sizes, int n_in,
                              void* d_out, int out_size)
{
    (void)in_sizes; (void)n_in; (void)out_size;
    const float* x    = (const float*)d_in[0];
    const float* Wqkv = (const float*)d_in[1];
    const float* bqkv = (const float*)d_in[2];
    const float* Wout = (const float*)d_in[3];
    const float* bout = (const float*)d_in[4];
    float* out = (float*)d_out;

    __nv_bfloat16 *xh, *xl, *wqh, *wql, *woh, *wol;
    __nv_bfloat16 *qh, *ql, *kh, *kl, *vh, *vl, *ath, *atl;
    cudaGetSymbolAddress((void**)&xh, g_x_hi);
    cudaGetSymbolAddress((void**)&xl, g_x_lo);
    cudaGetSymbolAddress((void**)&wqh, g_wq_hi);
    cudaGetSymbolAddress((void**)&wql, g_wq_lo);
    cudaGetSymbolAddress((void**)&woh, g_wo_hi);
    cudaGetSymbolAddress((void**)&wol, g_wo_lo);
    cudaGetSymbolAddress((void**)&qh, g_q_hi);
    cudaGetSymbolAddress((void**)&ql, g_q_lo);
    cudaGetSymbolAddress((void**)&kh, g_k_hi);
    cudaGetSymbolAddress((void**)&kl, g_k_lo);
    cudaGetSymbolAddress((void**)&vh, g_v_hi);
    cudaGetSymbolAddress((void**)&vl, g_v_lo);
    cudaGetSymbolAddress((void**)&ath, g_att_hi);
    cudaGetSymbolAddress((void**)&atl, g_att_lo);

    split_ew<<<(Bsz * Sq * Dm / 4) / 256, 256>>>(x, xh, xl);
    transpose_split<<<dim3(3 * Dm / 32, Dm / 32), dim3(32, 8)>>>(Wqkv, Dm, 3 * Dm, wqh, wql);
    transpose_split<<<dim3(Dm / 32, Dm / 32), dim3(32, 8)>>>(Wout, Dm, Dm, woh, wol);

    cudaFuncSetAttribute(gemm512, cudaFuncAttributeMaxDynamicSharedMemorySize, GEMM_SMEM);
    cudaFuncSetAttribute(flash_mma, cudaFuncAttributeMaxDynamicSharedMemorySize, FLASH_SMEM);

    // 1) QKV projection, epilogue scatters head-major bf16 hi/lo Q/K/V
    gemm512<<<dim3(3 * Dm / 128, Bsz * Sq / 128), 512, GEMM_SMEM>>>(
        Bsz * Sq, 3 * Dm, Dm, xh, xl, wqh, wql, bqkv, nullptr, 1,
        qh, ql, kh, kl, vh, vl);

    // 2) causal flash attention (tensor cores) -> att hi/lo
    flash_mma<<<dim3(Sq / 64, Bsz * Hn), 128, FLASH_SMEM>>>(
        qh, ql, kh, kl, vh, vl, ath, atl);

    // 3) output projection on raw-reshaped values
    gemm512<<<dim3(Dm / 128, Bsz * Sq / 128), 512, GEMM_SMEM>>>(
        Bsz * Sq, Dm, Dm, ath, atl, woh, wol, bout, out, 0,
        nullptr, nullptr, nullptr, nullptr, nullptr, nullptr);
}

// round 9
// speedup vs baseline: 2.4118x; 1.6576x over previous
#include <cuda_runtime.h>
#include <cuda_bf16.h>
#include <math.h>
#include <stdint.h>

// Problem constants
#define Bsz 2
#define Sq  2048
#define Dm  1024
#define Hn  16
#define HDm 64

// ---------------------------------------------------------------------------
// Scratch (__device__ globals; allocation-free rule)
// ---------------------------------------------------------------------------
#define HEADELEMS ((size_t)Bsz * Hn * Sq * HDm)
__device__ __nv_bfloat16 g_q_hi[HEADELEMS];
__device__ __nv_bfloat16 g_q_lo[HEADELEMS];
__device__ __nv_bfloat16 g_k_hi[HEADELEMS];
__device__ __nv_bfloat16 g_k_lo[HEADELEMS];
__device__ __nv_bfloat16 g_v_hi[HEADELEMS];
__device__ __nv_bfloat16 g_v_lo[HEADELEMS];
__device__ __nv_bfloat16 g_att_hi[HEADELEMS];     // raw-reshape layout
__device__ __nv_bfloat16 g_att_lo[HEADELEMS];
__device__ __nv_bfloat16 g_x_hi[(size_t)Bsz * Sq * Dm];
__device__ __nv_bfloat16 g_x_lo[(size_t)Bsz * Sq * Dm];
__device__ __nv_bfloat16 g_wq_hi[(size_t)3 * Dm * Dm];   // W_qkv^T [3072][1024]
__device__ __nv_bfloat16 g_wq_lo[(size_t)3 * Dm * Dm];
__device__ __nv_bfloat16 g_wo_hi[(size_t)Dm * Dm];       // W_out^T [1024][1024]
__device__ __nv_bfloat16 g_wo_lo[(size_t)Dm * Dm];

// ---------------------------------------------------------------------------
// Baseline-PTX helpers
// ---------------------------------------------------------------------------
__device__ __forceinline__ uint32_t smem_u32(const void* p) {
    uint32_t a;
    asm("{ .reg .u64 t; cvta.to.shared.u64 t, %1; cvt.u32.u64 %0, t; }" : "=r"(a) : "l"(p));
    return a;
}
__device__ __forceinline__ void cp_async16(uint32_t s, const void* g) {
    asm volatile("cp.async.cg.shared.global [%0], [%1], 16;\n" :: "r"(s), "l"(g));
}
__device__ __forceinline__ void cp_commit() {
    asm volatile("cp.async.commit_group;\n" ::: "memory");
}
__device__ __forceinline__ void cp_wait0() {
    asm volatile("cp.async.wait_group 0;\n" ::: "memory");
}
__device__ __forceinline__ void cp_wait1() {
    asm volatile("cp.async.wait_group 1;\n" ::: "memory");
}
__device__ __forceinline__ void ldm_x4(uint32_t* r, uint32_t addr) {
    asm volatile("ldmatrix.sync.aligned.m8n8.x4.shared.b16 {%0,%1,%2,%3}, [%4];"
                 : "=r"(r[0]), "=r"(r[1]), "=r"(r[2]), "=r"(r[3]) : "r"(addr));
}
__device__ __forceinline__ void ldm_x4_t(uint32_t* r, uint32_t addr) {
    asm volatile("ldmatrix.sync.aligned.m8n8.x4.trans.shared.b16 {%0,%1,%2,%3}, [%4];"
                 : "=r"(r[0]), "=r"(r[1]), "=r"(r[2]), "=r"(r[3]) : "r"(addr));
}
__device__ __forceinline__ void mma16816(float* d, const uint32_t* a,
                                         uint32_t b0, uint32_t b1) {
    asm volatile(
        "mma.sync.aligned.m16n8k16.row.col.f32.bf16.bf16.f32 "
        "{%0,%1,%2,%3},{%4,%5,%6,%7},{%8,%9},{%0,%1,%2,%3};"
        : "+f"(d[0]), "+f"(d[1]), "+f"(d[2]), "+f"(d[3])
        : "r"(a[0]), "r"(a[1]), "r"(a[2]), "r"(a[3]), "r"(b0), "r"(b1));
}
__device__ __forceinline__ uint32_t pack_bf2(float a, float b) {
    __nv_bfloat162 h = __floats2bfloat162_rn(a, b);
    return *(uint32_t*)&h;
}

// ---------------------------------------------------------------------------
// Conversion kernels
// ---------------------------------------------------------------------------
__global__ void split_ew(const float* __restrict__ A,
                         __nv_bfloat16* __restrict__ hi, __nv_bfloat16* __restrict__ lo)
{
    int i = blockIdx.x * blockDim.x + threadIdx.x;
    float4 v = ((const float4*)A)[i];
    __nv_bfloat16 h0 = __float2bfloat16(v.x), h1 = __float2bfloat16(v.y);
    __nv_bfloat16 h2 = __float2bfloat16(v.z), h3 = __float2bfloat16(v.w);
    __nv_bfloat162* H = (__nv_bfloat162*)hi;
    __nv_bfloat162* L = (__nv_bfloat162*)lo;
    H[2 * i]     = __nv_bfloat162(h0, h1);
    H[2 * i + 1] = __nv_bfloat162(h2, h3);
    L[2 * i]     = __nv_bfloat162(__float2bfloat16(v.x - __bfloat162float(h0)),
                                  __float2bfloat16(v.y - __bfloat162float(h1)));
    L[2 * i + 1] = __nv_bfloat162(__float2bfloat16(v.z - __bfloat162float(h2)),
                                  __float2bfloat16(v.w - __bfloat162float(h3)));
}

__global__ void transpose_split(const float* __restrict__ W, int K, int N,
                                __nv_bfloat16* __restrict__ Thi, __nv_bfloat16* __restrict__ Tlo)
{
    __shared__ float t[32][33];
    int n0 = blockIdx.x * 32, k0 = blockIdx.y * 32;
    int tx = threadIdx.x, ty = threadIdx.y;  // 32x8
#pragma unroll
    for (int r = ty; r < 32; r += 8)
        t[r][tx] = W[(size_t)(k0 + r) * N + n0 + tx];
    __syncthreads();
#pragma unroll
    for (int r = ty; r < 32; r += 8) {
        float v = t[tx][r];
        __nv_bfloat16 h = __float2bfloat16(v);
        size_t dst = (size_t)(n0 + r) * K + k0 + tx;
        Thi[dst] = h;
        Tlo[dst] = __float2bfloat16(v - __bfloat162float(h));
    }
}

// ---------------------------------------------------------------------------
// bf16x2-split GEMM via mma.sync. R5-proven shape: 256 threads, 8 warps
// (2m x 4n), warp tile 64x32, 4:1 mma:ldmatrix. K-chunk 32, double-buffered.
// __launch_bounds__(256,2): cap regs at 128 so 2 CTAs/SM co-reside.
// mode 0: C = A@B^T + bias (fp32). mode 1: scatter head-major Q/K/V hi/lo.
// ---------------------------------------------------------------------------
#define TILE_B   10240                       // 128 rows * 80 bytes
#define GEMM_SMEM (2 * 4 * TILE_B)           // 81920 (40KB/CTA... x2 CTA = 160KB)

__global__ __launch_bounds__(256, 2) void gemm_mma(
    int M, int N, int K,
    const __nv_bfloat16* __restrict__ Ahi, const __nv_bfloat16* __restrict__ Alo,
    const __nv_bfloat16* __restrict__ Bhi, const __nv_bfloat16* __restrict__ Blo,
    const float* __restrict__ bias, float* __restrict__ C, int mode,
    __nv_bfloat16* __restrict__ qh, __nv_bfloat16* __restrict__ ql,
    __nv_bfloat16* __restrict__ kh, __nv_bfloat16* __restrict__ kl,
    __nv_bfloat16* __restrict__ vh, __nv_bfloat16* __restrict__ vl)
{
    extern __shared__ char smc[];
    const uint32_t sb = smem_u32(smc);
    const int tid  = threadIdx.x;
    const int wid  = tid >> 5;
    const int lane = tid & 31;
    const int by = blockIdx.y * 128;
    const int bx = blockIdx.x * 128;
    const int wm = wid & 1;        // 0..1  (64-row band)
    const int wn = wid >> 1;       // 0..3  (32-col band)

    auto tile = [&](int buf, int t) -> uint32_t {
        return sb + (uint32_t)(buf * 4 + t) * TILE_B;
    };
    auto load_tile = [&](uint32_t sbase, const __nv_bfloat16* src, int row0, int k0) {
#pragma unroll
        for (int g = tid; g < 512; g += 256) {
            int r = g >> 2, s = g & 3;
            cp_async16(sbase + (uint32_t)(r * 80 + s * 16),
                       (const char*)(src + (size_t)(row0 + r) * K + k0) + s * 16);
        }
    };
    auto load_chunk = [&](int buf, int k0) {
        load_tile(tile(buf, 0), Ahi, by, k0);
        load_tile(tile(buf, 1), Alo, by, k0);
        load_tile(tile(buf, 2), Bhi, bx, k0);
        load_tile(tile(buf, 3), Blo, bx, k0);
        cp_commit();
    };

    float acc[4][4][4];
#pragma unroll
    for (int i = 0; i < 4; i++)
#pragma unroll
        for (int j = 0; j < 4; j++)
#pragma unroll
            for (int k = 0; k < 4; k++) acc[i][j][k] = 0.f;

    const int NC = K / 32;
    load_chunk(0, 0);

    const uint32_t lrow = (uint32_t)(lane & 15);
    const uint32_t lkb  = (uint32_t)((lane >> 4) * 8) * 2;

    for (int c = 0; c < NC; c++) {
        const int cur = c & 1;
        if (c + 1 < NC) { load_chunk(cur ^ 1, (c + 1) * 32); cp_wait1(); }
        else            { cp_wait0(); }
        __syncthreads();

        const uint32_t sAh = tile(cur, 0), sAl = tile(cur, 1);
        const uint32_t sBh = tile(cur, 2), sBl = tile(cur, 3);

#pragma unroll
        for (int ks = 0; ks < 2; ks++) {
            const uint32_t kby = (uint32_t)(ks * 16) * 2 + lkb;
            uint32_t a[4][4], bh0[4], bh1[4], bl0[4], bl1[4];

#pragma unroll
            for (int mt = 0; mt < 4; mt++)
                ldm_x4(a[mt], sAh + (uint32_t)((wm * 64 + mt * 16) + lrow) * 80 + kby);
            ldm_x4(bh0, sBh + (uint32_t)(wn * 32 + lrow) * 80 + kby);
            ldm_x4(bh1, sBh + (uint32_t)(wn * 32 + 16 + lrow) * 80 + kby);
            ldm_x4(bl0, sBl + (uint32_t)(wn * 32 + lrow) * 80 + kby);
            ldm_x4(bl1, sBl + (uint32_t)(wn * 32 + 16 + lrow) * 80 + kby);

            // pass 1: Ahi @ Bhi ; pass 2: Ahi @ Blo
#pragma unroll
            for (int mt = 0; mt < 4; mt++) {
                mma16816(acc[mt][0], a[mt], bh0[0], bh0[2]);
                mma16816(acc[mt][1], a[mt], bh0[1], bh0[3]);
                mma16816(acc[mt][2], a[mt], bh1[0], bh1[2]);
                mma16816(acc[mt][3], a[mt], bh1[1], bh1[3]);
            }
#pragma unroll
            for (int mt = 0; mt < 4; mt++) {
                mma16816(acc[mt][0], a[mt], bl0[0], bl0[2]);
                mma16816(acc[mt][1], a[mt], bl0[1], bl0[3]);
                mma16816(acc[mt][2], a[mt], bl1[0], bl1[2]);
                mma16816(acc[mt][3], a[mt], bl1[1], bl1[3]);
            }
            // pass 3: Alo @ Bhi
#pragma unroll
            for (int mt = 0; mt < 4; mt++)
                ldm_x4(a[mt], sAl + (uint32_t)((wm * 64 + mt * 16) + lrow) * 80 + kby);
#pragma unroll
            for (int mt = 0; mt < 4; mt++) {
                mma16816(acc[mt][0], a[mt], bh0[0], bh0[2]);
                mma16816(acc[mt][1], a[mt], bh0[1], bh0[3]);
                mma16816(acc[mt][2], a[mt], bh1[0], bh1[2]);
                mma16816(acc[mt][3], a[mt], bh1[1], bh1[3]);
            }
        }
        __syncthreads();
    }

    const int r0 = lane >> 2;
    const int c0 = (lane & 3) * 2;

    if (mode == 0) {
#pragma unroll
        for (int mt = 0; mt < 4; mt++) {
#pragma unroll
            for (int nt = 0; nt < 4; nt++) {
                int row = by + wm * 64 + mt * 16 + r0;
                int col = bx + wn * 32 + nt * 8 + c0;
                float b0 = bias[col], b1 = bias[col + 1];
                *(float2*)(C + (size_t)row * N + col) =
                    make_float2(acc[mt][nt][0] + b0, acc[mt][nt][1] + b1);
                *(float2*)(C + (size_t)(row + 8) * N + col) =
                    make_float2(acc[mt][nt][2] + b0, acc[mt][nt][3] + b1);
            }
        }
    } else {
        // scatter to head-major Q/K/V hi/lo. col0 is 32-aligned; 192/64 are
        // 32-multiples, so head and q/k/v selection are warp-uniform.
        int col0 = bx + wn * 32;
        int h = col0 / 192;
        int t = (col0 % 192) / 64;
        int hdb = col0 & 63;
        __nv_bfloat16* dh = (t == 0) ? qh : (t == 1) ? kh : vh;
        __nv_bfloat16* dl = (t == 0) ? ql : (t == 1) ? kl : vl;
#pragma unroll
        for (int mt = 0; mt < 4; mt++) {
#pragma unroll
            for (int nt = 0; nt < 4; nt++) {
                int gr = by + wm * 64 + mt * 16 + r0;
                int bb = gr >> 11, s = gr & 2047;
                int hd = hdb + nt * 8 + c0;
                int col = col0 + nt * 8 + c0;
                float b0 = bias[col], b1 = bias[col + 1];
                size_t d0 = (((size_t)(bb * Hn + h)) * Sq + s) * HDm + hd;
                size_t d1 = d0 + 8 * HDm;
#pragma unroll
                for (int rr = 0; rr < 2; rr++) {
                    float v0 = acc[mt][nt][2 * rr + 0] + b0;
                    float v1 = acc[mt][nt][2 * rr + 1] + b1;
                    __nv_bfloat162 hh = __floats2bfloat162_rn(v0, v1);
                    __nv_bfloat162 ll = __floats2bfloat162_rn(
                        v0 - __bfloat162float(hh.x), v1 - __bfloat162float(hh.y));
                    size_t d = rr ? d1 : d0;
                    *(__nv_bfloat162*)(dh + d) = hh;
                    *(__nv_bfloat162*)(dl + d) = ll;
                }
            }
        }
    }
}

// ---------------------------------------------------------------------------
// Flash attention via mma.sync bf16 hi/lo (3-pass), causal, online softmax.
// CTA = 128 threads (4 warps), 64 q rows. __launch_bounds__(128,2): 2 CTAs/SM
// (2 x 90KB smem fits 228KB carveout) for latency hiding.
// ---------------------------------------------------------------------------
#define FTILE 9216                    // 64 * 72 * 2 bytes
#define FLASH_SMEM (2 * FTILE + 2 * 4 * FTILE)   // 92160

__global__ __launch_bounds__(128, 2) void flash_mma(
    const __nv_bfloat16* __restrict__ qh, const __nv_bfloat16* __restrict__ ql,
    const __nv_bfloat16* __restrict__ kh, const __nv_bfloat16* __restrict__ kl,
    const __nv_bfloat16* __restrict__ vh, const __nv_bfloat16* __restrict__ vl,
    __nv_bfloat16* __restrict__ ah, __nv_bfloat16* __restrict__ al)
{
    extern __shared__ char smc[];
    const uint32_t sb = smem_u32(smc);
    const int tid  = threadIdx.x;
    const int wid  = tid >> 5;
    const int lane = tid & 31;
    const int bh = blockIdx.y;
    const int qb = blockIdx.x;

    const uint32_t sQh = sb, sQl = sb + FTILE;
    auto kvtile = [&](int buf, int t) -> uint32_t {
        return sb + 2 * FTILE + (uint32_t)(buf * 4 + t) * FTILE;
    };

    const char* hb_q  = (const char*)(qh + (size_t)bh * Sq * HDm);
    const char* hb_ql = (const char*)(ql + (size_t)bh * Sq * HDm);
    const char* hb_k  = (const char*)(kh + (size_t)bh * Sq * HDm);
    const char* hb_kl = (const char*)(kl + (size_t)bh * Sq * HDm);
    const char* hb_v  = (const char*)(vh + (size_t)bh * Sq * HDm);
    const char* hb_vl = (const char*)(vl + (size_t)bh * Sq * HDm);

    auto load_tile = [&](uint32_t dst, const char* srcbase, int row0) {
#pragma unroll
        for (int g = tid; g < 512; g += 128) {
            int r = g >> 3, ch = g & 7;
            cp_async16(dst + (uint32_t)(r * 144 + ch * 16),
                       srcbase + (size_t)(row0 + r) * 128 + ch * 16);
        }
    };
    auto load_kv = [&](int buf, int jb) {
        load_tile(kvtile(buf, 0), hb_k,  jb * 64);
        load_tile(kvtile(buf, 1), hb_kl, jb * 64);
        load_tile(kvtile(buf, 2), hb_v,  jb * 64);
        load_tile(kvtile(buf, 3), hb_vl, jb * 64);
        cp_commit();
    };

    load_tile(sQh, hb_q,  qb * 64);
    load_tile(sQl, hb_ql, qb * 64);
    load_kv(0, 0);

    float o[8][4];
#pragma unroll
    for (int t = 0; t < 8; t++)
#pragma unroll
        for (int j = 0; j < 4; j++) o[t][j] = 0.f;
    float m0 = -1e30f, m1 = -1e30f, l0 = 0.f, l1 = 0.f;

    const uint32_t lrow = (uint32_t)(lane & 15);
    const uint32_t lkb  = (uint32_t)((lane >> 4) * 16);
    const uint32_t qoff = (uint32_t)(wid * 16 + (lane & 15)) * 144 + lkb;
    const int rloc0 = wid * 16 + (lane >> 2);
    const int cpair = (lane & 3) * 2;
    const float scale = 0.125f;

    for (int jb = 0; jb <= qb; jb++) {
        const int buf = jb & 1;
        if (jb + 1 <= qb) { load_kv(buf ^ 1, jb + 1); cp_wait1(); }
        else              { cp_wait0(); }
        __syncthreads();

        const uint32_t sKh = kvtile(buf, 0), sKl = kvtile(buf, 1);
        const uint32_t sVh = kvtile(buf, 2), sVl = kvtile(buf, 3);

        // ----- S = Q @ K^T (3-pass hi/lo) -----
        float s[8][4];
#pragma unroll
        for (int t = 0; t < 8; t++)
#pragma unroll
            for (int j = 0; j < 4; j++) s[t][j] = 0.f;

#pragma unroll
        for (int kc = 0; kc < 4; kc++) {
            const uint32_t kof = (uint32_t)(kc * 32);
            uint32_t a[4], a2[4], b[4][4];
            ldm_x4(a,  sQh + qoff + kof);
            ldm_x4(a2, sQl + qoff + kof);
#pragma unroll
            for (int g = 0; g < 4; g++)
                ldm_x4(b[g], sKh + (uint32_t)(g * 16 + (int)lrow) * 144 + lkb + kof);
#pragma unroll
            for (int g = 0; g < 4; g++) {
                mma16816(s[2 * g + 0], a,  b[g][0], b[g][2]);
                mma16816(s[2 * g + 1], a,  b[g][1], b[g][3]);
                mma16816(s[2 * g + 0], a2, b[g][0], b[g][2]);
                mma16816(s[2 * g + 1], a2, b[g][1], b[g][3]);
            }
#pragma unroll
            for (int g = 0; g < 4; g++)
                ldm_x4(b[g], sKl + (uint32_t)(g * 16 + (int)lrow) * 144 + lkb + kof);
#pragma unroll
            for (int g = 0; g < 4; g++) {
                mma16816(s[2 * g + 0], a, b[g][0], b[g][2]);
                mma16816(s[2 * g + 1], a, b[g][1], b[g][3]);
            }
        }

        if (jb == qb) {
#pragma unroll
            for (int t = 0; t < 8; t++) {
                int c = 8 * t + cpair;
#pragma unroll
                for (int j = 0; j < 4; j++) {
                    int cc = c + (j & 1);
                    int rr = rloc0 + (j >> 1) * 8;
                    s[t][j] = (cc > rr) ? -1e30f : s[t][j] * scale;
                }
            }
        } else {
#pragma unroll
            for (int t = 0; t < 8; t++)
#pragma unroll
                for (int j = 0; j < 4; j++) s[t][j] *= scale;
        }

        // ----- online softmax -----
        float rm0 = -1e30f, rm1 = -1e30f;
#pragma unroll
        for (int t = 0; t < 8; t++) {
            rm0 = fmaxf(rm0, fmaxf(s[t][0], s[t][1]));
            rm1 = fmaxf(rm1, fmaxf(s[t][2], s[t][3]));
        }
        rm0 = fmaxf(rm0, __shfl_xor_sync(0xffffffffu, rm0, 1, 4));
        rm0 = fmaxf(rm0, __shfl_xor_sync(0xffffffffu, rm0, 2, 4));
        rm1 = fmaxf(rm1, __shfl_xor_sync(0xffffffffu, rm1, 1, 4));
        rm1 = fmaxf(rm1, __shfl_xor_sync(0xffffffffu, rm1, 2, 4));

        float mn0 = fmaxf(m0, rm0), mn1 = fmaxf(m1, rm1);
        float corr0 = __expf(m0 - mn0), corr1 = __expf(m1 - mn1);
        m0 = mn0; m1 = mn1;

        float rs0 = 0.f, rs1 = 0.f;
#pragma unroll
        for (int t = 0; t < 8; t++) {
            s[t][0] = __expf(s[t][0] - mn0); rs0 += s[t][0];
            s[t][1] = __expf(s[t][1] - mn0); rs0 += s[t][1];
            s[t][2] = __expf(s[t][2] - mn1); rs1 += s[t][2];
            s[t][3] = __expf(s[t][3] - mn1); rs1 += s[t][3];
        }
        rs0 += __shfl_xor_sync(0xffffffffu, rs0, 1, 4);
        rs0 += __shfl_xor_sync(0xffffffffu, rs0, 2, 4);
        rs1 += __shfl_xor_sync(0xffffffffu, rs1, 1, 4);
        rs1 += __shfl_xor_sync(0xffffffffu, rs1, 2, 4);
        l0 = l0 * corr0 + rs0;
        l1 = l1 * corr1 + rs1;
#pragma unroll
        for (int t = 0; t < 8; t++) {
            o[t][0] *= corr0; o[t][1] *= corr0;
            o[t][2] *= corr1; o[t][3] *= corr1;
        }

        // ----- P -> bf16 hi/lo A-fragments -----
        uint32_t ph[8][2], pl[8][2];
#pragma unroll
        for (int t = 0; t < 8; t++) {
            __nv_bfloat162 h0 = __floats2bfloat162_rn(s[t][0], s[t][1]);
            __nv_bfloat162 h1 = __floats2bfloat162_rn(s[t][2], s[t][3]);
            ph[t][0] = *(uint32_t*)&h0;
            ph[t][1] = *(uint32_t*)&h1;
            pl[t][0] = pack_bf2(s[t][0] - __bfloat162float(h0.x),
                                s[t][1] - __bfloat162float(h0.y));
            pl[t][1] = pack_bf2(s[t][2] - __bfloat162float(h1.x),
                                s[t][3] - __bfloat162float(h1.y));
        }

        // ----- O += P @ V (3-pass) -----
        const uint32_t vrow = (uint32_t)(lane & 15) * 144;
        const uint32_t vhd  = (uint32_t)((lane >> 4) * 8) * 2;
#pragma unroll
        for (int kc = 0; kc < 4; kc++) {
            uint32_t a[4]  = {ph[2 * kc][0], ph[2 * kc][1], ph[2 * kc + 1][0], ph[2 * kc + 1][1]};
            uint32_t a2[4] = {pl[2 * kc][0], pl[2 * kc][1], pl[2 * kc + 1][0], pl[2 * kc + 1][1]};
            const uint32_t rb = (uint32_t)(kc * 16) * 144;
#pragma unroll
            for (int hg = 0; hg < 4; hg++) {
                uint32_t bv[4];
                ldm_x4_t(bv, sVh + rb + vrow + (uint32_t)(hg * 16) * 2 + vhd);
                mma16816(o[2 * hg + 0], a,  bv[0], bv[1]);
                mma16816(o[2 * hg + 1], a,  bv[2], bv[3]);
                mma16816(o[2 * hg + 0], a2, bv[0], bv[1]);
                mma16816(o[2 * hg + 1], a2, bv[2], bv[3]);
                ldm_x4_t(bv, sVl + rb + vrow + (uint32_t)(hg * 16) * 2 + vhd);
                mma16816(o[2 * hg + 0], a, bv[0], bv[1]);
                mma16816(o[2 * hg + 1], a, bv[2], bv[3]);
            }
        }
        __syncthreads();
    }

    // ----- epilogue -----
    const float inv0 = 1.0f / l0, inv1 = 1.0f / l1;
    const size_t rb0 = ((size_t)bh * Sq + (size_t)(qb * 64 + rloc0)) * HDm;
    const size_t rb1 = rb0 + 8 * HDm;
#pragma unroll
    for (int t = 0; t < 8; t++) {
        int hd = 8 * t + cpair;
        float v0 = o[t][0] * inv0, v1 = o[t][1] * inv0;
        float v2 = o[t][2] * inv1, v3 = o[t][3] * inv1;
        __nv_bfloat162 h0 = __floats2bfloat162_rn(v0, v1);
        __nv_bfloat162 h1 = __floats2bfloat162_rn(v2, v3);
        *(__nv_bfloat162*)(ah + rb0 + hd) = h0;
        *(__nv_bfloat162*)(ah + rb1 + hd) = h1;
        *(__nv_bfloat162*)(al + rb0 + hd) = __floats2bfloat162_rn(
            v0 - __bfloat162float(h0.x), v1 - __bfloat162float(h0.y));
        *(__nv_bfloat162*)(al + rb1 + hd) = __floats2bfloat162_rn(
            v2 - __bfloat162float(h1.x), v3 - __bfloat162float(h1.y));
    }
}

// ---------------------------------------------------------------------------
extern "C" void kernel_launch(void* const* d_in, const int* in_sizes, int n_in,
                              void* d_out, int out_size)
{
    (void)in_sizes; (void)n_in; (void)out_size;
    const float* x    = (const float*)d_in[0];
    const float* Wqkv = (const float*)d_in[1];
    const float* bqkv = (const float*)d_in[2];
    const float* Wout = (const float*)d_in[3];
    const float* bout = (const float*)d_in[4];
    float* out = (float*)d_out;

    __nv_bfloat16 *xh, *xl, *wqh, *wql, *woh, *wol;
    __nv_bfloat16 *qh, *ql, *kh, *kl, *vh, *vl, *ath, *atl;
    cudaGetSymbolAddress((void**)&xh, g_x_hi);
    cudaGetSymbolAddress((void**)&xl, g_x_lo);
    cudaGetSymbolAddress((void**)&wqh, g_wq_hi);
    cudaGetSymbolAddress((void**)&wql, g_wq_lo);
    cudaGetSymbolAddress((void**)&woh, g_wo_hi);
    cudaGetSymbolAddress((void**)&wol, g_wo_lo);
    cudaGetSymbolAddress((void**)&qh, g_q_hi);
    cudaGetSymbolAddress((void**)&ql, g_q_lo);
    cudaGetSymbolAddress((void**)&kh, g_k_hi);
    cudaGetSymbolAddress((void**)&kl, g_k_lo);
    cudaGetSymbolAddress((void**)&vh, g_v_hi);
    cudaGetSymbolAddress((void**)&vl, g_v_lo);
    cudaGetSymbolAddress((void**)&ath, g_att_hi);
    cudaGetSymbolAddress((void**)&atl, g_att_lo);

    split_ew<<<(Bsz * Sq * Dm / 4) / 256, 256>>>(x, xh, xl);
    transpose_split<<<dim3(3 * Dm / 32, Dm / 32), dim3(32, 8)>>>(Wqkv, Dm, 3 * Dm, wqh, wql);
    transpose_split<<<dim3(Dm / 32, Dm / 32), dim3(32, 8)>>>(Wout, Dm, Dm, woh, wol);

    cudaFuncSetAttribute(gemm_mma, cudaFuncAttributeMaxDynamicSharedMemorySize, GEMM_SMEM);
    cudaFuncSetAttribute(flash_mma, cudaFuncAttributeMaxDynamicSharedMemorySize, FLASH_SMEM);

    // 1) QKV projection, scatter head-major bf16 hi/lo Q/K/V
    gemm_mma<<<dim3(3 * Dm / 128, Bsz * Sq / 128), 256, GEMM_SMEM>>>(
        Bsz * Sq, 3 * Dm, Dm, xh, xl, wqh, wql, bqkv, nullptr, 1,
        qh, ql, kh, kl, vh, vl);

    // 2) causal flash attention (tensor cores)
    flash_mma<<<dim3(Sq / 64, Bsz * Hn), 128, FLASH_SMEM>>>(
        qh, ql, kh, kl, vh, vl, ath, atl);

    // 3) output projection on raw-reshaped values
    gemm_mma<<<dim3(Dm / 128, Bsz * Sq / 128), 256, GEMM_SMEM>>>(
        Bsz * Sq, Dm, Dm, ath, atl, woh, wol, bout, out, 0,
        nullptr, nullptr, nullptr, nullptr, nullptr, nullptr);
}